// round 13
// baseline (speedup 1.0000x reference)
#include <cuda_runtime.h>
#include <cuda_bf16.h>
#include <cuda_fp16.h>

// Problem constants: I, J are [B=2, 1, D=192, H=192, W=192] fp32.
#define Bv   2
#define Dv   192
#define Hv   192
#define Wv   192
#define HWv  (Hv * Wv)              // 36864
#define HW4v (HWv / 4)              // 9216 (half4 granules per plane)
#define DHWv (Dv * Hv * Wv)         // 7077888
#define Nv   ((size_t)Bv * DHWv)    // 14155776
#define K_SUM 729.0f

#define HT     16                   // output H rows per p12 block
#define HTILES (Hv / HT)            // 12
#define HROWS  (HT + 8)             // 24 input rows incl. halo

#define DCH    48                   // D-chunk for pass3 (R9 geometry)
#define DCHN   (Dv / DCH)           // 4
#define P3GRID (Bv * (Hv / 4) * DCHN)   // 384

// Intermediates: 5 planar fp16 channels of HW-box-sums + fp16 copies of I, J.
__device__ __align__(16) __half g_bufB[5 * Nv];
__device__ __align__(16) __half g_Ih[Nv];
__device__ __align__(16) __half g_Jh[Nv];
__device__ double g_acc;
__device__ unsigned g_count;        // zero-init; self-resetting

static __device__ __forceinline__ float4 f4z() { return make_float4(0.f, 0.f, 0.f, 0.f); }

static __device__ __forceinline__ void f4acc(float4& a, float4 b) {
    a.x += b.x; a.y += b.y; a.z += b.z; a.w += b.w;
}
static __device__ __forceinline__ void f4dec(float4& a, float4 b) {
    a.x -= b.x; a.y -= b.y; a.z -= b.z; a.w -= b.w;
}

static __device__ __forceinline__ void st_half4(__half* dst, float4 v) {
    __half2 a = __floats2half2_rn(v.x, v.y);
    __half2 b = __floats2half2_rn(v.z, v.w);
    uint2 u;
    u.x = *(unsigned*)&a;
    u.y = *(unsigned*)&b;
    *(uint2*)dst = u;
}

static __device__ __forceinline__ float4 h4f(uint2 u) {
    __half2 a = *(__half2*)&u.x;
    __half2 b = *(__half2*)&u.y;
    float2 fa = __half22float2(a), fb = __half22float2(b);
    return make_float4(fa.x, fa.y, fb.x, fb.y);
}

// ---------------------------------------------------------------------------
// Fused pass: products + W box-sum + H box-sum (round-10 version, ~62.5us).
// ---------------------------------------------------------------------------
__global__ void __launch_bounds__(192) p12_k(const float* __restrict__ I,
                                             const float* __restrict__ J) {
    extern __shared__ char smraw[];
    __half* wsh = (__half*)smraw;            // [5][HROWS][Wv] fp16

    const int tid  = threadIdx.x;
    const int tile = blockIdx.x % HTILES;
    const int slab = blockIdx.x / HTILES;    // b*Dv + d
    const int h0   = tile * HT;
    const size_t sbase = (size_t)slab * HWv;

    if (blockIdx.x == 0 && tid == 0) g_acc = 0.0;

    // Phase A: 576 units = 24 rows x 24 8-wide segments; 3 per thread.
#pragma unroll
    for (int rep = 0; rep < 3; rep++) {
        const int u    = tid + rep * 192;
        const int r    = u / 24;             // row in tile (0..23)
        const int seg  = u % 24;             // 8-wide W segment
        const int h_in = h0 - 4 + r;
        const bool okh = (h_in >= 0) && (h_in < Hv);
        const size_t rb = sbase + (size_t)h_in * Wv;
        const int wb   = seg * 8 - 4;        // window start (16 floats)

        float fI[16], fJ[16];
#pragma unroll
        for (int j = 0; j < 4; j++) {
            int c0 = wb + 4 * j;
            float4 a = f4z(), bq = f4z();
            if (okh && c0 >= 0 && c0 <= Wv - 4) {
                a  = *(const float4*)(I + rb + c0);
                bq = *(const float4*)(J + rb + c0);
            }
            fI[4*j+0] = a.x;  fI[4*j+1] = a.y;  fI[4*j+2] = a.z;  fI[4*j+3] = a.w;
            fJ[4*j+0] = bq.x; fJ[4*j+1] = bq.y; fJ[4*j+2] = bq.z; fJ[4*j+3] = bq.w;
        }

        // Emit fp16 I,J for pass3 (interior rows; tiles partition H).
        if (okh && h_in >= h0 && h_in < h0 + HT) {
            st_half4(g_Ih + rb + wb + 4, make_float4(fI[4], fI[5], fI[6], fI[7]));
            st_half4(g_Ih + rb + wb + 8, make_float4(fI[8], fI[9], fI[10], fI[11]));
            st_half4(g_Jh + rb + wb + 4, make_float4(fJ[4], fJ[5], fJ[6], fJ[7]));
            st_half4(g_Jh + rb + wb + 8, make_float4(fJ[8], fJ[9], fJ[10], fJ[11]));
        }

#pragma unroll
        for (int ch = 0; ch < 5; ch++) {
            float t[16];
#pragma unroll
            for (int k = 0; k < 16; k++)
                t[k] = (ch == 0) ? fI[k] : (ch == 1) ? fJ[k] :
                       (ch == 2) ? fI[k] * fI[k] : (ch == 3) ? fJ[k] * fJ[k] :
                       fI[k] * fJ[k];
            float S = t[0]+t[1]+t[2]+t[3]+t[4]+t[5]+t[6]+t[7]+t[8];
            float4 oa, ob;
            oa.x = S;
            S += t[9]  - t[0]; oa.y = S;
            S += t[10] - t[1]; oa.z = S;
            S += t[11] - t[2]; oa.w = S;
            S += t[12] - t[3]; ob.x = S;
            S += t[13] - t[4]; ob.y = S;
            S += t[14] - t[5]; ob.z = S;
            S += t[15] - t[6]; ob.w = S;
            __half* wp = wsh + (ch * HROWS + r) * Wv + seg * 8;
            st_half4(wp, oa);
            st_half4(wp + 4, ob);
        }
    }
    __syncthreads();

    // Phase B: 240 (channel, column) units; 9-slot packed register ring.
    int u = tid;
#pragma unroll
    for (int rep = 0; rep < 2; rep++) {
        if (u < 240) {
            const int ch  = u / 48;
            const int col = u % 48;
            const uint2* wsc = (const uint2*)(wsh + ch * HROWS * Wv);
            __half* outp = g_bufB + (size_t)ch * Nv + sbase + (size_t)h0 * Wv + col * 4;

            uint2 ring[9];
            float4 s = f4z();
#pragma unroll
            for (int m = 0; m < 9; m++) {
                ring[m] = wsc[m * 48 + col];
                f4acc(s, h4f(ring[m]));
            }
#pragma unroll
            for (int t = 0; t < 16; t++) {
                st_half4(outp + (size_t)t * Wv, s);
                if (t < 15) {
                    uint2 add = wsc[(t + 9) * 48 + col];
                    f4acc(s, h4f(add));
                    f4dec(s, h4f(ring[t % 9]));
                    ring[t % 9] = add;
                }
            }
        }
        u += 192;
    }
}

// ---------------------------------------------------------------------------
// Pass 3 (R9 geometry: 192 threads = 48 col-groups x 4 h-rows, uint2
// ownership, DCH=48, 61KB smem ring; single wave of 384 blocks).
// Tweaks vs R9: unroll 8 (2x outstanding LDGs) and ring reads hoisted
// before the combine so LDS latency overlaps FMA work.
// ---------------------------------------------------------------------------
__global__ void __launch_bounds__(192) pass3_k(float* __restrict__ out) {
    extern __shared__ uint2 ring[];          // [5][8][192]
    __shared__ float red[6];

    const int tid   = threadIdx.x;
    const int cg    = tid % 48;              // column group (cols 4cg..4cg+3)
    const int hrow  = tid / 48;              // 0..3
    const int bid   = blockIdx.x;
    const int chunk = bid % DCHN;
    const int bh4   = bid / DCHN;
    const int b     = bh4 / (Hv / 4);
    const int h     = (bh4 % (Hv / 4)) * 4 + hrow;
    const int d0    = chunk * DCH;

    const size_t base4 = ((size_t)b * DHWv + (size_t)h * Wv) / 4 + cg;

    const uint2* __restrict__ c0 = (const uint2*)g_bufB;
    const uint2* __restrict__ c1 = (const uint2*)(g_bufB + Nv);
    const uint2* __restrict__ c2 = (const uint2*)(g_bufB + 2 * Nv);
    const uint2* __restrict__ c3 = (const uint2*)(g_bufB + 3 * Nv);
    const uint2* __restrict__ c4 = (const uint2*)(g_bufB + 4 * Nv);
    const uint2* __restrict__ Ih = (const uint2*)g_Ih;
    const uint2* __restrict__ Jh = (const uint2*)g_Jh;

#define RING(ch, slot) ring[((ch) * 8 + (slot)) * 192 + tid]

    float4 s0 = f4z(), s1 = f4z(), s2 = f4z(), s3 = f4z(), s4 = f4z();
    const uint2 uz = make_uint2(0u, 0u);

#pragma unroll
    for (int m = 0; m < 8; m++) {            // planes d0-4 .. d0+3
        int d = d0 - 4 + m;
        uint2 v0 = uz, v1 = uz, v2 = uz, v3 = uz, v4 = uz;
        if (d >= 0) {
            size_t o = base4 + (size_t)d * HW4v;
            v0 = c0[o]; v1 = c1[o]; v2 = c2[o]; v3 = c3[o]; v4 = c4[o];
        }
        RING(0, m) = v0; RING(1, m) = v1; RING(2, m) = v2;
        RING(3, m) = v3; RING(4, m) = v4;
        f4acc(s0, h4f(v0)); f4acc(s1, h4f(v1)); f4acc(s2, h4f(v2));
        f4acc(s3, h4f(v3)); f4acc(s4, h4f(v4));
    }

    float local = 0.f;
    const float inv_k = 1.0f / K_SUM;

#pragma unroll 8
    for (int t = 0; t < DCH; t++) {
        int d = d0 + t;
        size_t o = base4 + (size_t)d * HW4v;
        const int slot = t & 7;

        // Leading-plane global loads (independent, issue first).
        uint2 l0 = uz, l1 = uz, l2 = uz, l3 = uz, l4 = uz;
        if (d + 4 < Dv) {
            size_t ol = o + 4 * (size_t)HW4v;
            l0 = c0[ol]; l1 = c1[ol]; l2 = c2[ol]; l3 = c3[ol]; l4 = c4[ol];
        }
        // Ring reads hoisted: overlap LDS latency with the combine below.
        uint2 r0 = RING(0, slot), r1 = RING(1, slot), r2 = RING(2, slot);
        uint2 r3 = RING(3, slot), r4 = RING(4, slot);

        f4acc(s0, h4f(l0)); f4acc(s1, h4f(l1)); f4acc(s2, h4f(l2));
        f4acc(s3, h4f(l3)); f4acc(s4, h4f(l4));

        float4 iv = h4f(Ih[o]);
        float4 jv = h4f(Jh[o]);

#define COMB(C) { \
        float iu = iv.C * inv_k, ju = jv.C * inv_k; \
        float cross = s4.C - s0.C * ju - s1.C * iu + iu * ju * K_SUM; \
        float ivar  = s2.C - 2.f * s0.C * iu + iu * iu * K_SUM; \
        float jvar  = s3.C - 2.f * s1.C * ju + ju * ju * K_SUM; \
        local += (cross * cross) / (ivar * jvar + 1e-5f); }

        COMB(x) COMB(y) COMB(z) COMB(w)
#undef COMB

        f4dec(s0, h4f(r0)); f4dec(s1, h4f(r1)); f4dec(s2, h4f(r2));
        f4dec(s3, h4f(r3)); f4dec(s4, h4f(r4));
        RING(0, slot) = l0; RING(1, slot) = l1; RING(2, slot) = l2;
        RING(3, slot) = l3; RING(4, slot) = l4;
    }
#undef RING

    // Reduce 192 threads -> 1 double atomic; last block finalizes.
    float v = local;
#pragma unroll
    for (int off = 16; off > 0; off >>= 1)
        v += __shfl_down_sync(0xffffffffu, v, off);
    if ((tid & 31) == 0) red[tid >> 5] = v;
    __syncthreads();
    if (tid == 0) {
        float s = 0.f;
#pragma unroll
        for (int i = 0; i < 6; i++) s += red[i];
        atomicAdd(&g_acc, (double)s);
        __threadfence();
        unsigned done = atomicAdd(&g_count, 1u);
        if (done == (unsigned)(P3GRID - 1)) {
            g_count = 0;                     // self-reset for next replay
            out[0] = (float)(-g_acc / (double)Nv);
        }
    }
}

extern "C" void kernel_launch(void* const* d_in, const int* in_sizes, int n_in,
                              void* d_out, int out_size) {
    const float* I = (const float*)d_in[0];
    const float* J = (const float*)d_in[1];
    float* out = (float*)d_out;

    const int p12_smem = 5 * HROWS * Wv * 2;                  // 46080 B
    const int p3_smem  = 5 * 8 * 192 * (int)sizeof(uint2);    // 61440 B
    cudaFuncSetAttribute(p12_k, cudaFuncAttributeMaxDynamicSharedMemorySize, p12_smem);
    cudaFuncSetAttribute(pass3_k, cudaFuncAttributeMaxDynamicSharedMemorySize, p3_smem);

    p12_k<<<Bv * Dv * HTILES, 192, p12_smem>>>(I, J);         // 4608 blocks
    pass3_k<<<P3GRID, 192, p3_smem>>>(out);                   // 384 blocks
}

// round 14
// speedup vs baseline: 1.6209x; 1.6209x over previous
#include <cuda_runtime.h>
#include <cuda_bf16.h>
#include <cuda_fp16.h>

// Problem constants: I, J are [B=2, 1, D=192, H=192, W=192] fp32.
#define Bv   2
#define Dv   192
#define Hv   192
#define Wv   192
#define HWv  (Hv * Wv)              // 36864
#define HW4v (HWv / 4)              // 9216 (half4 granules per plane)
#define DHWv (Dv * Hv * Wv)         // 7077888
#define Nv   ((size_t)Bv * DHWv)    // 14155776
#define K_SUM 729.0f

#define HT     16                   // output H rows per p12 block
#define HTILES (Hv / HT)            // 12
#define HROWS  (HT + 8)             // 24 input rows incl. halo

#define DCH    48                   // D-chunk for pass3 (R9 geometry)
#define DCHN   (Dv / DCH)           // 4
#define P3GRID (Bv * (Hv / 4) * DCHN)   // 384

// Intermediates: 5 planar fp16 channels of HW-box-sums + fp16 copies of I, J.
__device__ __align__(16) __half g_bufB[5 * Nv];
__device__ __align__(16) __half g_Ih[Nv];
__device__ __align__(16) __half g_Jh[Nv];
__device__ double g_acc;
__device__ unsigned g_count;        // zero-init; self-resetting

static __device__ __forceinline__ float4 f4z() { return make_float4(0.f, 0.f, 0.f, 0.f); }

static __device__ __forceinline__ void f4acc(float4& a, float4 b) {
    a.x += b.x; a.y += b.y; a.z += b.z; a.w += b.w;
}
static __device__ __forceinline__ void f4dec(float4& a, float4 b) {
    a.x -= b.x; a.y -= b.y; a.z -= b.z; a.w -= b.w;
}

static __device__ __forceinline__ void st_half4(__half* dst, float4 v) {
    __half2 a = __floats2half2_rn(v.x, v.y);
    __half2 b = __floats2half2_rn(v.z, v.w);
    uint2 u;
    u.x = *(unsigned*)&a;
    u.y = *(unsigned*)&b;
    *(uint2*)dst = u;
}

static __device__ __forceinline__ float4 h4f(uint2 u) {
    __half2 a = *(__half2*)&u.x;
    __half2 b = *(__half2*)&u.y;
    float2 fa = __half22float2(a), fb = __half22float2(b);
    return make_float4(fa.x, fa.y, fb.x, fb.y);
}

// ---------------------------------------------------------------------------
// Fused pass: products + W box-sum + H box-sum (round-10 version, ~62.5us).
// ---------------------------------------------------------------------------
__global__ void __launch_bounds__(192) p12_k(const float* __restrict__ I,
                                             const float* __restrict__ J) {
    extern __shared__ char smraw[];
    __half* wsh = (__half*)smraw;            // [5][HROWS][Wv] fp16

    const int tid  = threadIdx.x;
    const int tile = blockIdx.x % HTILES;
    const int slab = blockIdx.x / HTILES;    // b*Dv + d
    const int h0   = tile * HT;
    const size_t sbase = (size_t)slab * HWv;

    if (blockIdx.x == 0 && tid == 0) g_acc = 0.0;

    // Phase A: 576 units = 24 rows x 24 8-wide segments; 3 per thread.
#pragma unroll
    for (int rep = 0; rep < 3; rep++) {
        const int u    = tid + rep * 192;
        const int r    = u / 24;             // row in tile (0..23)
        const int seg  = u % 24;             // 8-wide W segment
        const int h_in = h0 - 4 + r;
        const bool okh = (h_in >= 0) && (h_in < Hv);
        const size_t rb = sbase + (size_t)h_in * Wv;
        const int wb   = seg * 8 - 4;        // window start (16 floats)

        float fI[16], fJ[16];
#pragma unroll
        for (int j = 0; j < 4; j++) {
            int c0 = wb + 4 * j;
            float4 a = f4z(), bq = f4z();
            if (okh && c0 >= 0 && c0 <= Wv - 4) {
                a  = *(const float4*)(I + rb + c0);
                bq = *(const float4*)(J + rb + c0);
            }
            fI[4*j+0] = a.x;  fI[4*j+1] = a.y;  fI[4*j+2] = a.z;  fI[4*j+3] = a.w;
            fJ[4*j+0] = bq.x; fJ[4*j+1] = bq.y; fJ[4*j+2] = bq.z; fJ[4*j+3] = bq.w;
        }

        // Emit fp16 I,J for pass3 (interior rows; tiles partition H).
        if (okh && h_in >= h0 && h_in < h0 + HT) {
            st_half4(g_Ih + rb + wb + 4, make_float4(fI[4], fI[5], fI[6], fI[7]));
            st_half4(g_Ih + rb + wb + 8, make_float4(fI[8], fI[9], fI[10], fI[11]));
            st_half4(g_Jh + rb + wb + 4, make_float4(fJ[4], fJ[5], fJ[6], fJ[7]));
            st_half4(g_Jh + rb + wb + 8, make_float4(fJ[8], fJ[9], fJ[10], fJ[11]));
        }

#pragma unroll
        for (int ch = 0; ch < 5; ch++) {
            float t[16];
#pragma unroll
            for (int k = 0; k < 16; k++)
                t[k] = (ch == 0) ? fI[k] : (ch == 1) ? fJ[k] :
                       (ch == 2) ? fI[k] * fI[k] : (ch == 3) ? fJ[k] * fJ[k] :
                       fI[k] * fJ[k];
            float S = t[0]+t[1]+t[2]+t[3]+t[4]+t[5]+t[6]+t[7]+t[8];
            float4 oa, ob;
            oa.x = S;
            S += t[9]  - t[0]; oa.y = S;
            S += t[10] - t[1]; oa.z = S;
            S += t[11] - t[2]; oa.w = S;
            S += t[12] - t[3]; ob.x = S;
            S += t[13] - t[4]; ob.y = S;
            S += t[14] - t[5]; ob.z = S;
            S += t[15] - t[6]; ob.w = S;
            __half* wp = wsh + (ch * HROWS + r) * Wv + seg * 8;
            st_half4(wp, oa);
            st_half4(wp + 4, ob);
        }
    }
    __syncthreads();

    // Phase B: 240 (channel, column) units; 9-slot packed register ring.
    int u = tid;
#pragma unroll
    for (int rep = 0; rep < 2; rep++) {
        if (u < 240) {
            const int ch  = u / 48;
            const int col = u % 48;
            const uint2* wsc = (const uint2*)(wsh + ch * HROWS * Wv);
            __half* outp = g_bufB + (size_t)ch * Nv + sbase + (size_t)h0 * Wv + col * 4;

            uint2 ring[9];
            float4 s = f4z();
#pragma unroll
            for (int m = 0; m < 9; m++) {
                ring[m] = wsc[m * 48 + col];
                f4acc(s, h4f(ring[m]));
            }
#pragma unroll
            for (int t = 0; t < 16; t++) {
                st_half4(outp + (size_t)t * Wv, s);
                if (t < 15) {
                    uint2 add = wsc[(t + 9) * 48 + col];
                    f4acc(s, h4f(add));
                    f4dec(s, h4f(ring[t % 9]));
                    ring[t % 9] = add;
                }
            }
        }
        u += 192;
    }
}

// ---------------------------------------------------------------------------
// Pass 3 (round-9 VERBATIM: 192 threads = 48 col-groups x 4 h-rows, uint2
// ownership, DCH=48, 61KB smem ring, unroll 4, original load/combine/ring
// order — measured 57.2us, regs 70). Fused finalize.
// ---------------------------------------------------------------------------
__global__ void __launch_bounds__(192) pass3_k(float* __restrict__ out) {
    extern __shared__ uint2 ring[];          // [5][8][192]
    __shared__ float red[6];

    const int tid   = threadIdx.x;
    const int cg    = tid % 48;              // column group (cols 4cg..4cg+3)
    const int hrow  = tid / 48;              // 0..3
    const int bid   = blockIdx.x;
    const int chunk = bid % DCHN;
    const int bh4   = bid / DCHN;
    const int b     = bh4 / (Hv / 4);
    const int h     = (bh4 % (Hv / 4)) * 4 + hrow;
    const int d0    = chunk * DCH;

    const size_t base4 = ((size_t)b * DHWv + (size_t)h * Wv) / 4 + cg;

    const uint2* __restrict__ c0 = (const uint2*)g_bufB;
    const uint2* __restrict__ c1 = (const uint2*)(g_bufB + Nv);
    const uint2* __restrict__ c2 = (const uint2*)(g_bufB + 2 * Nv);
    const uint2* __restrict__ c3 = (const uint2*)(g_bufB + 3 * Nv);
    const uint2* __restrict__ c4 = (const uint2*)(g_bufB + 4 * Nv);
    const uint2* __restrict__ Ih = (const uint2*)g_Ih;
    const uint2* __restrict__ Jh = (const uint2*)g_Jh;

#define RING(ch, slot) ring[((ch) * 8 + (slot)) * 192 + tid]

    float4 s0 = f4z(), s1 = f4z(), s2 = f4z(), s3 = f4z(), s4 = f4z();
    const uint2 uz = make_uint2(0u, 0u);

#pragma unroll
    for (int m = 0; m < 8; m++) {            // planes d0-4 .. d0+3
        int d = d0 - 4 + m;
        uint2 v0 = uz, v1 = uz, v2 = uz, v3 = uz, v4 = uz;
        if (d >= 0) {
            size_t o = base4 + (size_t)d * HW4v;
            v0 = c0[o]; v1 = c1[o]; v2 = c2[o]; v3 = c3[o]; v4 = c4[o];
        }
        RING(0, m) = v0; RING(1, m) = v1; RING(2, m) = v2;
        RING(3, m) = v3; RING(4, m) = v4;
        f4acc(s0, h4f(v0)); f4acc(s1, h4f(v1)); f4acc(s2, h4f(v2));
        f4acc(s3, h4f(v3)); f4acc(s4, h4f(v4));
    }

    float local = 0.f;
    const float inv_k = 1.0f / K_SUM;

#pragma unroll 4
    for (int t = 0; t < DCH; t++) {
        int d = d0 + t;
        size_t o = base4 + (size_t)d * HW4v;

        uint2 l0 = uz, l1 = uz, l2 = uz, l3 = uz, l4 = uz;
        if (d + 4 < Dv) {
            size_t ol = o + 4 * (size_t)HW4v;
            l0 = c0[ol]; l1 = c1[ol]; l2 = c2[ol]; l3 = c3[ol]; l4 = c4[ol];
        }
        f4acc(s0, h4f(l0)); f4acc(s1, h4f(l1)); f4acc(s2, h4f(l2));
        f4acc(s3, h4f(l3)); f4acc(s4, h4f(l4));

        float4 iv = h4f(Ih[o]);
        float4 jv = h4f(Jh[o]);

#define COMB(C) { \
        float iu = iv.C * inv_k, ju = jv.C * inv_k; \
        float cross = s4.C - s0.C * ju - s1.C * iu + iu * ju * K_SUM; \
        float ivar  = s2.C - 2.f * s0.C * iu + iu * iu * K_SUM; \
        float jvar  = s3.C - 2.f * s1.C * ju + ju * ju * K_SUM; \
        local += (cross * cross) / (ivar * jvar + 1e-5f); }

        COMB(x) COMB(y) COMB(z) COMB(w)
#undef COMB

        int slot = t & 7;
        f4dec(s0, h4f(RING(0, slot))); f4dec(s1, h4f(RING(1, slot)));
        f4dec(s2, h4f(RING(2, slot))); f4dec(s3, h4f(RING(3, slot)));
        f4dec(s4, h4f(RING(4, slot)));
        RING(0, slot) = l0; RING(1, slot) = l1; RING(2, slot) = l2;
        RING(3, slot) = l3; RING(4, slot) = l4;
    }
#undef RING

    // Reduce 192 threads -> 1 double atomic; last block finalizes.
    float v = local;
#pragma unroll
    for (int off = 16; off > 0; off >>= 1)
        v += __shfl_down_sync(0xffffffffu, v, off);
    if ((tid & 31) == 0) red[tid >> 5] = v;
    __syncthreads();
    if (tid == 0) {
        float s = 0.f;
#pragma unroll
        for (int i = 0; i < 6; i++) s += red[i];
        atomicAdd(&g_acc, (double)s);
        __threadfence();
        unsigned done = atomicAdd(&g_count, 1u);
        if (done == (unsigned)(P3GRID - 1)) {
            g_count = 0;                     // self-reset for next replay
            out[0] = (float)(-g_acc / (double)Nv);
        }
    }
}

extern "C" void kernel_launch(void* const* d_in, const int* in_sizes, int n_in,
                              void* d_out, int out_size) {
    const float* I = (const float*)d_in[0];
    const float* J = (const float*)d_in[1];
    float* out = (float*)d_out;

    const int p12_smem = 5 * HROWS * Wv * 2;                  // 46080 B
    const int p3_smem  = 5 * 8 * 192 * (int)sizeof(uint2);    // 61440 B
    cudaFuncSetAttribute(p12_k, cudaFuncAttributeMaxDynamicSharedMemorySize, p12_smem);
    cudaFuncSetAttribute(pass3_k, cudaFuncAttributeMaxDynamicSharedMemorySize, p3_smem);

    p12_k<<<Bv * Dv * HTILES, 192, p12_smem>>>(I, J);         // 4608 blocks
    pass3_k<<<P3GRID, 192, p3_smem>>>(out);                   // 384 blocks
}